// round 16
// baseline (speedup 1.0000x reference)
#include <cuda_runtime.h>
#include <cuda_fp16.h>
#include <stdint.h>
#include <math.h>

#define N_ROWS 4096
#define DIMS   1024
#define NCLS   64
#define NT     32               // 4096/128 tiles per dim
#define NTRI   (NT * (NT + 1) / 2)   // 528 lower-triangular tiles
#define INV_T  14.285714285714286f

#define NCHUNK 16               // K=1024 in BK=64 chunks
#define STAGE_BYTES 32768       // A 16KB + B 16KB
#define SM_RMASK (2 * STAGE_BYTES)             // 65536
#define SM_CMASK (SM_RMASK + 1024)
#define SM_ROWP  (SM_CMASK + 1024)
#define SM_ROWS  (SM_ROWP + 512)
#define SM_COLP  (SM_ROWS + 512)
#define SM_COLS  (SM_COLP + 512)
#define SMEM_TOTAL (SM_COLS + 512)             // 69632 B -> 2 CTAs/SM

#define FIN_BLOCKS 64

// ---------------- device scratch -------------------------------------------
__device__ __half g_h[N_ROWS * DIMS];           // 8 MB fp16 embeddings
__device__ unsigned long long g_mask[N_ROWS];
__device__ float g_w[N_ROWS];
__device__ float g_bce_part[N_ROWS];
__device__ float g_pp[NT * N_ROWS];
__device__ float g_ps[NT * N_ROWS];
__device__ float g_fl[FIN_BLOCKS], g_fb[FIN_BLOCKS];
__device__ int   g_fc[FIN_BLOCKS];
__device__ unsigned int g_ticket;               // static-init 0; self-resets

// ---------------- PTX helpers (baseline ISA only) ----------------------------
__device__ __forceinline__ uint32_t smem_u32(const void* p) {
    uint32_t a;
    asm("{ .reg .u64 t; cvta.to.shared.u64 t, %1; cvt.u32.u64 %0, t; }" : "=r"(a) : "l"(p));
    return a;
}
#define CP16(dst, src) \
    asm volatile("cp.async.cg.shared.global [%0], [%1], 16;" :: "r"(dst), "l"(src))
#define CP_COMMIT() asm volatile("cp.async.commit_group;")
#define CP_WAIT0()  asm volatile("cp.async.wait_group 0;")
#define LDSM4(r, a) \
    asm volatile("ldmatrix.sync.aligned.m8n8.x4.shared.b16 {%0,%1,%2,%3}, [%4];" \
        : "=r"((r)[0]), "=r"((r)[1]), "=r"((r)[2]), "=r"((r)[3]) : "r"(a))
#define MMA16816(c, a, b0, b1) \
    asm volatile("mma.sync.aligned.m16n8k16.row.col.f32.f16.f16.f32 " \
        "{%0,%1,%2,%3},{%4,%5,%6,%7},{%8,%9},{%0,%1,%2,%3};" \
        : "+f"((c)[0]), "+f"((c)[1]), "+f"((c)[2]), "+f"((c)[3]) \
        : "r"((a)[0]), "r"((a)[1]), "r"((a)[2]), "r"((a)[3]), "r"(b0), "r"(b1))

// ---------------- kernel A: fused convert (blocks 0..2047) + prep (2048..2559)
__global__ void fused_prep_kernel(const float* __restrict__ emb,
                                  const float* __restrict__ logits,
                                  const int* __restrict__ labels) {
    if (blockIdx.x < 2048) {
        // ---- convert: fp32 -> fp16, row-major -------------------------------
        const int idx = blockIdx.x * 256 + threadIdx.x;     // 8 elems per thread
        const float4* src = (const float4*)(emb + (size_t)idx * 8);
        const float4 x0 = src[0], x1 = src[1];
        const float v[8] = {x0.x, x0.y, x0.z, x0.w, x1.x, x1.y, x1.z, x1.w};
        uint32_t hw[4];
#pragma unroll
        for (int i = 0; i < 4; i++) {
            const __half h0 = __float2half_rn(v[2*i]);
            const __half h1 = __float2half_rn(v[2*i+1]);
            hw[i] = ((uint32_t)__half_as_ushort(h1) << 16) | __half_as_ushort(h0);
        }
        ((uint4*)g_h)[idx] = make_uint4(hw[0], hw[1], hw[2], hw[3]);
    } else {
        // ---- prep: 1 warp per row, 2 classes per lane -----------------------
        const int row = (blockIdx.x - 2048) * 8 + (threadIdx.x >> 5);
        const int lane = threadIdx.x & 31;
        const float2 xx = *(const float2*)(logits + row * NCLS + lane * 2);
        const int2 ll = *(const int2*)(labels + row * NCLS + lane * 2);
        float bce = 0.f, wn = 0.f, wd = 0.f;
        unsigned long long mk = 0ull;
        const float xv[2] = {xx.x, xx.y};
        const int lv[2] = {ll.x, ll.y};
#pragma unroll
        for (int q = 0; q < 2; q++) {
            const float x = xv[q];
            const float y = (float)lv[q];
            bce += fmaxf(x, 0.f) - x * y + log1pf(expf(-fabsf(x)));
            const float pr = 1.f / (1.f + expf(-x));
            const float ent = -(pr * logf(pr + 1e-8f) + (1.f - pr) * logf(1.f - pr + 1e-8f));
            wn += ent * y;
            wd += y;
            if (lv[q]) mk |= 1ull << (lane * 2 + q);
        }
#pragma unroll
        for (int off = 16; off > 0; off >>= 1) {
            bce += __shfl_xor_sync(0xffffffffu, bce, off);
            wn  += __shfl_xor_sync(0xffffffffu, wn, off);
            wd  += __shfl_xor_sync(0xffffffffu, wd, off);
            mk  |= __shfl_xor_sync(0xffffffffu, mk, off);
        }
        if (lane == 0) {
            g_bce_part[row] = bce;
            g_w[row] = wn / (wd + 1e-8f);
            g_mask[row] = mk;
        }
    }
}

// ---------------- kernel C: symmetric fp16 mma.sync GEMM + fused softmax ----
__global__ __launch_bounds__(256, 2)
void sim_kernel() {
    extern __shared__ char smem[];
    const uint32_t sbase = smem_u32(smem);
    const int tid = threadIdx.x;
    const int wid = tid >> 5, lane = tid & 31;
    const int wr = wid & 3, wc = wid >> 2;          // warp grid 4x2

    // map linear bid -> (I, J), J <= I
    const int bid = blockIdx.x;
    int I = (int)((sqrtf(8.f * (float)bid + 1.f) - 1.f) * 0.5f);
    while ((I + 1) * (I + 2) / 2 <= bid) I++;
    while (I * (I + 1) / 2 > bid) I--;
    const int J = bid - I * (I + 1) / 2;
    const bool isDiag = (I == J);
    const int rowBase = I * 128;
    const int colBase = J * 128;

    unsigned long long* rmaskS = (unsigned long long*)(smem + SM_RMASK);
    unsigned long long* cmaskS = (unsigned long long*)(smem + SM_CMASK);
    float* rowP = (float*)(smem + SM_ROWP);
    float* rowS = (float*)(smem + SM_ROWS);
    float* colP = (float*)(smem + SM_COLP);
    float* colS = (float*)(smem + SM_COLS);

    if (tid < 128) {
        rmaskS[tid] = g_mask[rowBase + tid];
        cmaskS[tid] = g_mask[colBase + tid];
        rowP[tid] = 0.f; rowS[tid] = 0.f;
        colP[tid] = 0.f; colS[tid] = 0.f;
    }

    // ---- cp.async fill mapping: 128-byte rows, XOR-8 swizzle ----------------
    const int r0 = tid >> 3;                 // rows 0..31, step 32 per pass
    const int g0 = tid & 7;                  // 16B group within 128B row
    const uint32_t dstOff = (uint32_t)(r0 * 128 + ((g0 ^ (r0 & 7)) * 16));
    const size_t gOffA = (size_t)(rowBase + r0) * DIMS + g0 * 8;
    const size_t gOffB = (size_t)(colBase + r0) * DIMS + g0 * 8;

    // ---- ldmatrix addressing -------------------------------------------------
    const int aRow = wr * 32 + (lane & 15);
    const uint32_t aR7 = (uint32_t)(aRow & 7);
    const int bRow = wc * 64 + (lane & 15);
    const uint32_t bR7 = (uint32_t)(bRow & 7);
    const uint32_t laneG = lane >> 4;

    float acc[2][8][4];
#pragma unroll
    for (int i = 0; i < 2; i++)
#pragma unroll
        for (int j = 0; j < 8; j++)
#pragma unroll
            for (int k = 0; k < 4; k++) acc[i][j][k] = 0.f;

    // prologue: fill stage 0 with chunk 0
    {
        const uint32_t st = sbase;
#pragma unroll
        for (int i = 0; i < 4; i++) {
            CP16(st + dstOff + i * 4096,         g_h + gOffA + (size_t)i * 32 * DIMS);
            CP16(st + 16384 + dstOff + i * 4096, g_h + gOffB + (size_t)i * 32 * DIMS);
        }
        CP_COMMIT();
    }

    for (int c = 0; c < NCHUNK; c++) {
        CP_WAIT0();
        __syncthreads();
        // prefetch chunk c+1 into the other stage (consumed at iter c-1)
        if (c + 1 < NCHUNK) {
            const size_t kk = (size_t)(c + 1) * 64;
            const uint32_t st = sbase + ((c + 1) & 1) * STAGE_BYTES;
#pragma unroll
            for (int i = 0; i < 4; i++) {
                CP16(st + dstOff + i * 4096,         g_h + gOffA + kk + (size_t)i * 32 * DIMS);
                CP16(st + 16384 + dstOff + i * 4096, g_h + gOffB + kk + (size_t)i * 32 * DIMS);
            }
            CP_COMMIT();
        }

        const uint32_t st = sbase + (c & 1) * STAGE_BYTES;
#pragma unroll
        for (int ks = 0; ks < 4; ks++) {
            uint32_t a0[4], a1[4], b[4][4];
            const uint32_t gk = (uint32_t)(ks * 2) + laneG;
            LDSM4(a0, st + aRow * 128        + ((gk ^ aR7) * 16));
            LDSM4(a1, st + (aRow + 16) * 128 + ((gk ^ aR7) * 16));
#pragma unroll
            for (int n16 = 0; n16 < 4; n16++)
                LDSM4(b[n16], st + 16384 + (bRow + n16 * 16) * 128 + ((gk ^ bR7) * 16));
#pragma unroll
            for (int nt = 0; nt < 8; nt++) {
                const int n16 = nt >> 1, h = nt & 1;
                MMA16816(acc[0][nt], a0, b[n16][h], b[n16][h + 2]);
                MMA16816(acc[1][nt], a1, b[n16][h], b[n16][h + 2]);
            }
        }
    }

    // ---- fused epilogue ------------------------------------------------------
    const int g8 = lane >> 2;        // quad row 0..7
    const int cq = (lane & 3) * 2;   // quad col pair
    float cp[8][2], cs[8][2];
#pragma unroll
    for (int nt = 0; nt < 8; nt++) { cp[nt][0]=cp[nt][1]=cs[nt][0]=cs[nt][1]=0.f; }

#pragma unroll
    for (int mt = 0; mt < 2; mt++) {
#pragma unroll
        for (int h = 0; h < 2; h++) {
            const int rl = wr * 32 + mt * 16 + h * 8 + g8;
            const int gi = rowBase + rl;
            const unsigned long long rm = rmaskS[rl];
            float pa = 0.f, sa = 0.f;
#pragma unroll
            for (int nt = 0; nt < 8; nt++) {
#pragma unroll
                for (int j = 0; j < 2; j++) {
                    const int cl = wc * 64 + nt * 8 + cq + j;
                    if (!isDiag || colBase + cl != gi) {
                        const float e = __expf(acc[mt][nt][h * 2 + j] * INV_T);
                        const bool pos = (rm & cmaskS[cl]) != 0ull;
                        sa += e;
                        if (pos) pa += e;
                        cs[nt][j] += e;
                        if (pos) cp[nt][j] += e;
                    }
                }
            }
            pa += __shfl_xor_sync(0xffffffffu, pa, 1);
            pa += __shfl_xor_sync(0xffffffffu, pa, 2);
            sa += __shfl_xor_sync(0xffffffffu, sa, 1);
            sa += __shfl_xor_sync(0xffffffffu, sa, 2);
            if ((lane & 3) == 0) {
                atomicAdd(&rowP[rl], pa);
                atomicAdd(&rowS[rl], sa);
            }
        }
    }

    if (!isDiag) {
#pragma unroll
        for (int nt = 0; nt < 8; nt++) {
#pragma unroll
            for (int j = 0; j < 2; j++) {
                float p = cp[nt][j], s = cs[nt][j];
#pragma unroll
                for (int off = 4; off < 32; off <<= 1) {
                    p += __shfl_xor_sync(0xffffffffu, p, off);
                    s += __shfl_xor_sync(0xffffffffu, s, off);
                }
                if (g8 == 0) {
                    const int cl = wc * 64 + nt * 8 + cq + j;
                    atomicAdd(&colP[cl], p);
                    atomicAdd(&colS[cl], s);
                }
            }
        }
    }

    __syncthreads();
    if (tid < 128) {
        g_pp[J * N_ROWS + rowBase + tid] = rowP[tid];
        g_ps[J * N_ROWS + rowBase + tid] = rowS[tid];
        if (!isDiag) {
            g_pp[I * N_ROWS + colBase + tid] = colP[tid];
            g_ps[I * N_ROWS + colBase + tid] = colS[tid];
        }
    }
}

// ---------------- kernel D: per-row loss + ticketed final reduction ----------
__global__ void final_kernel(float* __restrict__ out) {
    const int tid = threadIdx.x;                  // 64 threads, 64 blocks
    const int row = blockIdx.x * 64 + tid;
    float pp = 0.f, ss = 0.f;
#pragma unroll
    for (int sp = 0; sp < NT; sp++) {
        pp += g_pp[sp * N_ROWS + row];
        ss += g_ps[sp * N_ROWS + row];
    }
    float ls = 0.f;
    int c = 0;
    if (pp > 0.f) { ls = -logf(pp / (ss + 1e-8f)) * g_w[row]; c = 1; }
    float bs = g_bce_part[row];

    const int lane = tid & 31;
    const int w = tid >> 5;
#pragma unroll
    for (int off = 16; off > 0; off >>= 1) {
        ls += __shfl_down_sync(0xffffffffu, ls, off);
        bs += __shfl_down_sync(0xffffffffu, bs, off);
        c  += __shfl_down_sync(0xffffffffu, c, off);
    }
    __shared__ float wl[2], wb[2];
    __shared__ int wcc[2];
    __shared__ int lastFlag;
    if (lane == 0) { wl[w] = ls; wb[w] = bs; wcc[w] = c; }
    __syncthreads();
    if (tid == 0) {
        g_fl[blockIdx.x] = wl[0] + wl[1];
        g_fb[blockIdx.x] = wb[0] + wb[1];
        g_fc[blockIdx.x] = wcc[0] + wcc[1];
        __threadfence();
        lastFlag = (atomicAdd(&g_ticket, 1u) == FIN_BLOCKS - 1);
    }
    __syncthreads();
    if (lastFlag) {
        // last block: reduce 64 per-block partials in fixed order
        float fls = *((volatile float*)&g_fl[tid]);
        float fbs = *((volatile float*)&g_fb[tid]);
        int fc = *((volatile int*)&g_fc[tid]);
#pragma unroll
        for (int off = 16; off > 0; off >>= 1) {
            fls += __shfl_down_sync(0xffffffffu, fls, off);
            fbs += __shfl_down_sync(0xffffffffu, fbs, off);
            fc  += __shfl_down_sync(0xffffffffu, fc, off);
        }
        if (lane == 0) { wl[w] = fls; wb[w] = fbs; wcc[w] = fc; }
        __syncthreads();
        if (tid == 0) {
            const float totL = wl[0] + wl[1];
            const float totB = wb[0] + wb[1];
            const int totC = wcc[0] + wcc[1];
            const float bce = totB / (float)(N_ROWS * NCLS);
            out[0] = bce + ((totC > 0) ? (totL / (float)totC) : 0.f);
            g_ticket = 0u;        // self-reset for next launch / graph replay
        }
    }
}

// ---------------- launch ------------------------------------------------------
extern "C" void kernel_launch(void* const* d_in, const int* in_sizes, int n_in,
                              void* d_out, int out_size) {
    (void)in_sizes; (void)n_in; (void)out_size;
    const float* emb    = (const float*)d_in[0];
    const float* logits = (const float*)d_in[1];
    const int*   labels = (const int*)d_in[2];
    float* out = (float*)d_out;

    cudaFuncSetAttribute(sim_kernel, cudaFuncAttributeMaxDynamicSharedMemorySize, SMEM_TOTAL);

    fused_prep_kernel<<<2560, 256>>>(emb, logits, labels);
    sim_kernel<<<NTRI, 256, SMEM_TOTAL>>>();
    final_kernel<<<FIN_BLOCKS, 64>>>(out);
}

// round 17
// speedup vs baseline: 1.0178x; 1.0178x over previous
#include <cuda_runtime.h>
#include <cuda_fp16.h>
#include <stdint.h>
#include <math.h>

#define N_ROWS 4096
#define DIMS   1024
#define NCLS   64
#define NT     32               // 4096/128 tiles per dim
#define NTRI   (NT * (NT + 1) / 2)   // 528 lower-triangular tiles
#define INV_T  14.285714285714286f

#define NCHUNK 16               // K=1024 in BK=64 chunks
#define STAGE_BYTES 32768       // A 16KB + B 16KB
#define SM_RMASK (2 * STAGE_BYTES)             // 65536
#define SM_CMASK (SM_RMASK + 1024)
#define SM_ROWP  (SM_CMASK + 1024)
#define SM_ROWS  (SM_ROWP + 512)
#define SM_COLP  (SM_ROWS + 512)
#define SM_COLS  (SM_COLP + 512)
#define SMEM_TOTAL (SM_COLS + 512)             // 69632 B -> 2 CTAs/SM

#define FIN_BLOCKS 64

// ---------------- device scratch -------------------------------------------
__device__ __half g_h[N_ROWS * DIMS];           // 8 MB fp16 embeddings
__device__ unsigned long long g_mask[N_ROWS];
__device__ float g_w[N_ROWS];
__device__ float g_bce_part[N_ROWS];
__device__ float g_pp[NT * N_ROWS];
__device__ float g_ps[NT * N_ROWS];
__device__ float g_fl[FIN_BLOCKS], g_fb[FIN_BLOCKS];
__device__ int   g_fc[FIN_BLOCKS];
__device__ unsigned int g_ticket;               // static-init 0; self-resets

// ---------------- PTX helpers (baseline ISA only) ----------------------------
__device__ __forceinline__ uint32_t smem_u32(const void* p) {
    uint32_t a;
    asm("{ .reg .u64 t; cvta.to.shared.u64 t, %1; cvt.u32.u64 %0, t; }" : "=r"(a) : "l"(p));
    return a;
}
#define CP16(dst, src) \
    asm volatile("cp.async.cg.shared.global [%0], [%1], 16;" :: "r"(dst), "l"(src))
#define CP_COMMIT() asm volatile("cp.async.commit_group;")
#define CP_WAIT0()  asm volatile("cp.async.wait_group 0;")
#define LDSM4(r, a) \
    asm volatile("ldmatrix.sync.aligned.m8n8.x4.shared.b16 {%0,%1,%2,%3}, [%4];" \
        : "=r"((r)[0]), "=r"((r)[1]), "=r"((r)[2]), "=r"((r)[3]) : "r"(a))
#define MMA16816(c, a, b0, b1) \
    asm volatile("mma.sync.aligned.m16n8k16.row.col.f32.f16.f16.f32 " \
        "{%0,%1,%2,%3},{%4,%5,%6,%7},{%8,%9},{%0,%1,%2,%3};" \
        : "+f"((c)[0]), "+f"((c)[1]), "+f"((c)[2]), "+f"((c)[3]) \
        : "r"((a)[0]), "r"((a)[1]), "r"((a)[2]), "r"((a)[3]), "r"(b0), "r"(b1))

// ---------------- kernel A: fused convert (blocks 0..2047) + prep (2048..2559)
__global__ void fused_prep_kernel(const float* __restrict__ emb,
                                  const float* __restrict__ logits,
                                  const int* __restrict__ labels) {
    if (blockIdx.x < 2048) {
        // ---- convert: fp32 -> fp16, row-major -------------------------------
        const int idx = blockIdx.x * 256 + threadIdx.x;     // 8 elems per thread
        const float4* src = (const float4*)(emb + (size_t)idx * 8);
        const float4 x0 = src[0], x1 = src[1];
        const float v[8] = {x0.x, x0.y, x0.z, x0.w, x1.x, x1.y, x1.z, x1.w};
        uint32_t hw[4];
#pragma unroll
        for (int i = 0; i < 4; i++) {
            const __half h0 = __float2half_rn(v[2*i]);
            const __half h1 = __float2half_rn(v[2*i+1]);
            hw[i] = ((uint32_t)__half_as_ushort(h1) << 16) | __half_as_ushort(h0);
        }
        ((uint4*)g_h)[idx] = make_uint4(hw[0], hw[1], hw[2], hw[3]);
    } else {
        // ---- prep: 1 warp per row, 2 classes per lane -----------------------
        const int row = (blockIdx.x - 2048) * 8 + (threadIdx.x >> 5);
        const int lane = threadIdx.x & 31;
        const float2 xx = *(const float2*)(logits + row * NCLS + lane * 2);
        const int2 ll = *(const int2*)(labels + row * NCLS + lane * 2);
        float bce = 0.f, wn = 0.f, wd = 0.f;
        unsigned long long mk = 0ull;
        const float xv[2] = {xx.x, xx.y};
        const int lv[2] = {ll.x, ll.y};
#pragma unroll
        for (int q = 0; q < 2; q++) {
            const float x = xv[q];
            const float y = (float)lv[q];
            bce += fmaxf(x, 0.f) - x * y + log1pf(expf(-fabsf(x)));
            const float pr = 1.f / (1.f + expf(-x));
            const float ent = -(pr * logf(pr + 1e-8f) + (1.f - pr) * logf(1.f - pr + 1e-8f));
            wn += ent * y;
            wd += y;
            if (lv[q]) mk |= 1ull << (lane * 2 + q);
        }
#pragma unroll
        for (int off = 16; off > 0; off >>= 1) {
            bce += __shfl_xor_sync(0xffffffffu, bce, off);
            wn  += __shfl_xor_sync(0xffffffffu, wn, off);
            wd  += __shfl_xor_sync(0xffffffffu, wd, off);
            mk  |= __shfl_xor_sync(0xffffffffu, mk, off);
        }
        if (lane == 0) {
            g_bce_part[row] = bce;
            g_w[row] = wn / (wd + 1e-8f);
            g_mask[row] = mk;
        }
    }
}

// ---------------- kernel C: symmetric fp16 mma.sync GEMM + fused softmax ----
__global__ __launch_bounds__(256, 2)
void sim_kernel() {
    extern __shared__ char smem[];
    const uint32_t sbase = smem_u32(smem);
    const int tid = threadIdx.x;
    const int wid = tid >> 5, lane = tid & 31;
    const int wr = wid & 3, wc = wid >> 2;          // warp grid 4x2

    // map linear bid -> (I, J), J <= I
    const int bid = blockIdx.x;
    int I = (int)((sqrtf(8.f * (float)bid + 1.f) - 1.f) * 0.5f);
    while ((I + 1) * (I + 2) / 2 <= bid) I++;
    while (I * (I + 1) / 2 > bid) I--;
    const int J = bid - I * (I + 1) / 2;
    const bool isDiag = (I == J);
    const int rowBase = I * 128;
    const int colBase = J * 128;

    unsigned long long* rmaskS = (unsigned long long*)(smem + SM_RMASK);
    unsigned long long* cmaskS = (unsigned long long*)(smem + SM_CMASK);
    float* rowP = (float*)(smem + SM_ROWP);
    float* rowS = (float*)(smem + SM_ROWS);
    float* colP = (float*)(smem + SM_COLP);
    float* colS = (float*)(smem + SM_COLS);

    if (tid < 128) {
        rmaskS[tid] = g_mask[rowBase + tid];
        cmaskS[tid] = g_mask[colBase + tid];
        rowP[tid] = 0.f; rowS[tid] = 0.f;
        colP[tid] = 0.f; colS[tid] = 0.f;
    }

    // ---- cp.async fill mapping: 128-byte rows, XOR-8 swizzle ----------------
    const int r0 = tid >> 3;                 // rows 0..31, step 32 per pass
    const int g0 = tid & 7;                  // 16B group within 128B row
    const uint32_t dstOff = (uint32_t)(r0 * 128 + ((g0 ^ (r0 & 7)) * 16));
    const size_t gOffA = (size_t)(rowBase + r0) * DIMS + g0 * 8;
    const size_t gOffB = (size_t)(colBase + r0) * DIMS + g0 * 8;

    // ---- ldmatrix addressing -------------------------------------------------
    const int aRow = wr * 32 + (lane & 15);
    const uint32_t aR7 = (uint32_t)(aRow & 7);
    const int bRow = wc * 64 + (lane & 15);
    const uint32_t bR7 = (uint32_t)(bRow & 7);
    const uint32_t laneG = lane >> 4;

    float acc[2][8][4];
#pragma unroll
    for (int i = 0; i < 2; i++)
#pragma unroll
        for (int j = 0; j < 8; j++)
#pragma unroll
            for (int k = 0; k < 4; k++) acc[i][j][k] = 0.f;

    // prologue: fill stage 0 with chunk 0
    {
        const uint32_t st = sbase;
#pragma unroll
        for (int i = 0; i < 4; i++) {
            CP16(st + dstOff + i * 4096,         g_h + gOffA + (size_t)i * 32 * DIMS);
            CP16(st + 16384 + dstOff + i * 4096, g_h + gOffB + (size_t)i * 32 * DIMS);
        }
        CP_COMMIT();
    }

    for (int c = 0; c < NCHUNK; c++) {
        CP_WAIT0();
        __syncthreads();
        // prefetch chunk c+1 into the other stage (consumed at iter c-1)
        if (c + 1 < NCHUNK) {
            const size_t kk = (size_t)(c + 1) * 64;
            const uint32_t st = sbase + ((c + 1) & 1) * STAGE_BYTES;
#pragma unroll
            for (int i = 0; i < 4; i++) {
                CP16(st + dstOff + i * 4096,         g_h + gOffA + kk + (size_t)i * 32 * DIMS);
                CP16(st + 16384 + dstOff + i * 4096, g_h + gOffB + kk + (size_t)i * 32 * DIMS);
            }
            CP_COMMIT();
        }

        const uint32_t st = sbase + (c & 1) * STAGE_BYTES;
#pragma unroll
        for (int ks = 0; ks < 4; ks++) {
            uint32_t a0[4], a1[4], b[4][4];
            const uint32_t gk = (uint32_t)(ks * 2) + laneG;
            LDSM4(a0, st + aRow * 128        + ((gk ^ aR7) * 16));
            LDSM4(a1, st + (aRow + 16) * 128 + ((gk ^ aR7) * 16));
#pragma unroll
            for (int n16 = 0; n16 < 4; n16++)
                LDSM4(b[n16], st + 16384 + (bRow + n16 * 16) * 128 + ((gk ^ bR7) * 16));
#pragma unroll
            for (int nt = 0; nt < 8; nt++) {
                const int n16 = nt >> 1, h = nt & 1;
                MMA16816(acc[0][nt], a0, b[n16][h], b[n16][h + 2]);
                MMA16816(acc[1][nt], a1, b[n16][h], b[n16][h + 2]);
            }
        }
    }

    // ---- fused epilogue ------------------------------------------------------
    const int g8 = lane >> 2;        // quad row 0..7
    const int cq = (lane & 3) * 2;   // quad col pair
    float cp[8][2], cs[8][2];
#pragma unroll
    for (int nt = 0; nt < 8; nt++) { cp[nt][0]=cp[nt][1]=cs[nt][0]=cs[nt][1]=0.f; }

#pragma unroll
    for (int mt = 0; mt < 2; mt++) {
#pragma unroll
        for (int h = 0; h < 2; h++) {
            const int rl = wr * 32 + mt * 16 + h * 8 + g8;
            const int gi = rowBase + rl;
            const unsigned long long rm = rmaskS[rl];
            float pa = 0.f, sa = 0.f;
#pragma unroll
            for (int nt = 0; nt < 8; nt++) {
#pragma unroll
                for (int j = 0; j < 2; j++) {
                    const int cl = wc * 64 + nt * 8 + cq + j;
                    if (!isDiag || colBase + cl != gi) {
                        const float e = __expf(acc[mt][nt][h * 2 + j] * INV_T);
                        const bool pos = (rm & cmaskS[cl]) != 0ull;
                        sa += e;
                        if (pos) pa += e;
                        cs[nt][j] += e;
                        if (pos) cp[nt][j] += e;
                    }
                }
            }
            pa += __shfl_xor_sync(0xffffffffu, pa, 1);
            pa += __shfl_xor_sync(0xffffffffu, pa, 2);
            sa += __shfl_xor_sync(0xffffffffu, sa, 1);
            sa += __shfl_xor_sync(0xffffffffu, sa, 2);
            if ((lane & 3) == 0) {
                atomicAdd(&rowP[rl], pa);
                atomicAdd(&rowS[rl], sa);
            }
        }
    }

    if (!isDiag) {
#pragma unroll
        for (int nt = 0; nt < 8; nt++) {
#pragma unroll
            for (int j = 0; j < 2; j++) {
                float p = cp[nt][j], s = cs[nt][j];
#pragma unroll
                for (int off = 4; off < 32; off <<= 1) {
                    p += __shfl_xor_sync(0xffffffffu, p, off);
                    s += __shfl_xor_sync(0xffffffffu, s, off);
                }
                if (g8 == 0) {
                    const int cl = wc * 64 + nt * 8 + cq + j;
                    atomicAdd(&colP[cl], p);
                    atomicAdd(&colS[cl], s);
                }
            }
        }
    }

    __syncthreads();
    if (tid < 128) {
        g_pp[J * N_ROWS + rowBase + tid] = rowP[tid];
        g_ps[J * N_ROWS + rowBase + tid] = rowS[tid];
        if (!isDiag) {
            g_pp[I * N_ROWS + colBase + tid] = colP[tid];
            g_ps[I * N_ROWS + colBase + tid] = colS[tid];
        }
    }
}

// ---------------- kernel D: per-row loss + ticketed final reduction ----------
__global__ void final_kernel(float* __restrict__ out) {
    const int tid = threadIdx.x;                  // 64 threads, 64 blocks
    const int row = blockIdx.x * 64 + tid;
    float pp = 0.f, ss = 0.f;
#pragma unroll
    for (int sp = 0; sp < NT; sp++) {
        pp += g_pp[sp * N_ROWS + row];
        ss += g_ps[sp * N_ROWS + row];
    }
    float ls = 0.f;
    int c = 0;
    if (pp > 0.f) { ls = -logf(pp / (ss + 1e-8f)) * g_w[row]; c = 1; }
    float bs = g_bce_part[row];

    const int lane = tid & 31;
    const int w = tid >> 5;
#pragma unroll
    for (int off = 16; off > 0; off >>= 1) {
        ls += __shfl_down_sync(0xffffffffu, ls, off);
        bs += __shfl_down_sync(0xffffffffu, bs, off);
        c  += __shfl_down_sync(0xffffffffu, c, off);
    }
    __shared__ float wl[2], wb[2];
    __shared__ int wcc[2];
    __shared__ int lastFlag;
    if (lane == 0) { wl[w] = ls; wb[w] = bs; wcc[w] = c; }
    __syncthreads();
    if (tid == 0) {
        g_fl[blockIdx.x] = wl[0] + wl[1];
        g_fb[blockIdx.x] = wb[0] + wb[1];
        g_fc[blockIdx.x] = wcc[0] + wcc[1];
        __threadfence();
        lastFlag = (atomicAdd(&g_ticket, 1u) == FIN_BLOCKS - 1);
    }
    __syncthreads();
    if (lastFlag) {
        // last block: reduce 64 per-block partials in fixed order
        float fls = *((volatile float*)&g_fl[tid]);
        float fbs = *((volatile float*)&g_fb[tid]);
        int fc = *((volatile int*)&g_fc[tid]);
#pragma unroll
        for (int off = 16; off > 0; off >>= 1) {
            fls += __shfl_down_sync(0xffffffffu, fls, off);
            fbs += __shfl_down_sync(0xffffffffu, fbs, off);
            fc  += __shfl_down_sync(0xffffffffu, fc, off);
        }
        if (lane == 0) { wl[w] = fls; wb[w] = fbs; wcc[w] = fc; }
        __syncthreads();
        if (tid == 0) {
            const float totL = wl[0] + wl[1];
            const float totB = wb[0] + wb[1];
            const int totC = wcc[0] + wcc[1];
            const float bce = totB / (float)(N_ROWS * NCLS);
            out[0] = bce + ((totC > 0) ? (totL / (float)totC) : 0.f);
            g_ticket = 0u;        // self-reset for next launch / graph replay
        }
    }
}

// ---------------- launch ------------------------------------------------------
extern "C" void kernel_launch(void* const* d_in, const int* in_sizes, int n_in,
                              void* d_out, int out_size) {
    (void)in_sizes; (void)n_in; (void)out_size;
    const float* emb    = (const float*)d_in[0];
    const float* logits = (const float*)d_in[1];
    const int*   labels = (const int*)d_in[2];
    float* out = (float*)d_out;

    cudaFuncSetAttribute(sim_kernel, cudaFuncAttributeMaxDynamicSharedMemorySize, SMEM_TOTAL);

    fused_prep_kernel<<<2560, 256>>>(emb, logits, labels);
    sim_kernel<<<NTRI, 256, SMEM_TOTAL>>>();
    final_kernel<<<FIN_BLOCKS, 64>>>(out);
}